// round 12
// baseline (speedup 1.0000x reference)
#include <cuda_runtime.h>
#include <cuda_bf16.h>
#include <cstdint>

// ---------------- problem constants ----------------
#define L_SEQ    2048
#define D_MODEL  1024
#define D_INNER  2048
#define D_XB     512
#define D_STATE  16
#define DT_RANK  64
#define KCONV    4
#define G_HEADS  128
#define GX_HEADS 32
#define D_PROJ   5184
#define NPAD1    5248          // D_PROJ padded to multiple of 128

#define OFF_Z    0
#define OFF_X    2048
#define OFF_B    2560
#define OFF_C    3072
#define OFF_DT   5120

// scan chunking
#define CH       64
#define NCH      32            // L_SEQ / CH
#define NBLK     (G_HEADS * NCH)   // 4096 scan blocks

// ---------------- scratch (static device globals; no runtime allocation) ----
__device__ float g_zx   [L_SEQ * D_PROJ];
__device__ float g_delta[L_SEQ * D_INNER];
__device__ float g_xconv[L_SEQ * D_XB];

__device__ float g_P [L_SEQ * D_INNER];        // dt pre-activation (16.8MB)
__device__ float g_H [NBLK * 256];             // scan publish buffer
__device__ int   g_flag[NBLK];
__device__ int   g_ticket;

__device__ __nv_bfloat16 g_ahi [L_SEQ * D_INNER];
__device__ __nv_bfloat16 g_alo [L_SEQ * D_INNER];
__device__ __nv_bfloat16 g_w1hi[NPAD1 * D_MODEL];
__device__ __nv_bfloat16 g_w1lo[NPAD1 * D_MODEL];
__device__ __nv_bfloat16 g_w2hi[D_MODEL * D_INNER];
__device__ __nv_bfloat16 g_w2lo[D_MODEL * D_INNER];
__device__ __nv_bfloat16 g_dtrhi[L_SEQ * DT_RANK];
__device__ __nv_bfloat16 g_dtrlo[L_SEQ * DT_RANK];
__device__ __nv_bfloat16 g_wdthi[D_INNER * DT_RANK];
__device__ __nv_bfloat16 g_wdtlo[D_INNER * DT_RANK];

// ================= low-level helpers =========================================
__device__ __forceinline__ uint32_t smem_u32(const void* p) {
    return (uint32_t)__cvta_generic_to_shared(p);
}
__device__ __forceinline__ void cpasync16(uint32_t saddr, const void* g) {
    asm volatile("cp.async.cg.shared.global [%0], [%1], 16;" :: "r"(saddr), "l"(g));
}
__device__ __forceinline__ void ldsm4(uint32_t* r, uint32_t addr) {
    asm volatile("ldmatrix.sync.aligned.m8n8.x4.shared.b16 {%0,%1,%2,%3}, [%4];"
        : "=r"(r[0]), "=r"(r[1]), "=r"(r[2]), "=r"(r[3]) : "r"(addr));
}
__device__ __forceinline__ void mma16816(float* d, const uint32_t* a, const uint32_t* b) {
    asm volatile("mma.sync.aligned.m16n8k16.row.col.f32.bf16.bf16.f32 "
        "{%0,%1,%2,%3}, {%4,%5,%6,%7}, {%8,%9}, {%0,%1,%2,%3};"
        : "+f"(d[0]), "+f"(d[1]), "+f"(d[2]), "+f"(d[3])
        : "r"(a[0]), "r"(a[1]), "r"(a[2]), "r"(a[3]), "r"(b[0]), "r"(b[1]));
}
__device__ __forceinline__ uint32_t sw32(uint32_t off) {
    return off ^ ((off >> 3) & 0x70);
}

// ================= fp32 -> bf16 hi/lo conversion =============================
__global__ void __launch_bounds__(256)
convert_hilo(const float* __restrict__ in, __nv_bfloat16* __restrict__ hi,
             __nv_bfloat16* __restrict__ lo, int count)
{
    int i = (blockIdx.x * 256 + threadIdx.x) * 4;
    if (i >= count) return;
    float4 v = *(const float4*)(in + i);
    float vv[4] = {v.x, v.y, v.z, v.w};
    __nv_bfloat16 h[4], l[4];
    #pragma unroll
    for (int j = 0; j < 4; ++j) {
        h[j] = __float2bfloat16_rn(vv[j]);
        l[j] = __float2bfloat16_rn(vv[j] - __bfloat162float(h[j]));
    }
    *(uint2*)(hi + i) = *(uint2*)h;
    *(uint2*)(lo + i) = *(uint2*)l;
}

// ================= transpose W [K,N] -> [Npad,K] bf16 hi/lo ==================
__global__ void __launch_bounds__(256)
transpose_wt(const float* __restrict__ W, __nv_bfloat16* __restrict__ Thi,
             __nv_bfloat16* __restrict__ Tlo, int K, int N)
{
    __shared__ float tile[32][33];
    int n0 = blockIdx.x * 32;
    int k0 = blockIdx.y * 32;
    int tx = threadIdx.x & 31, ty = threadIdx.x >> 5;
    #pragma unroll
    for (int r = 0; r < 4; ++r) {
        int k = k0 + ty + r * 8;
        int n = n0 + tx;
        tile[ty + r * 8][tx] = (n < N) ? W[(size_t)k * N + n] : 0.f;
    }
    __syncthreads();
    #pragma unroll
    for (int r = 0; r < 4; ++r) {
        int n = n0 + ty + r * 8;
        int k = k0 + tx;
        float v = tile[tx][ty + r * 8];
        __nv_bfloat16 h = __float2bfloat16_rn(v);
        Thi[(size_t)n * K + k] = h;
        Tlo[(size_t)n * K + k] = __float2bfloat16_rn(v - __bfloat162float(h));
    }
}

// ================= split-bf16 warp-MMA GEMM (R9 measured-best) ===============
// CTA tile (MF*32) x 128, 8 warps (2m x 4n), warp tile (MF*16) x 32.
// Pipeline stage = TWO k=16 slices; 3 stages; persistent tiles.
#define NSTAGE   3

template<int MF>
__global__ void __launch_bounds__(256, 2)
gemm_tc_kernel(const __nv_bfloat16* __restrict__ Ahi, const __nv_bfloat16* __restrict__ Alo,
               const __nv_bfloat16* __restrict__ Bhi, const __nv_bfloat16* __restrict__ Blo,
               float* __restrict__ C, int Nreal, int K, int tilesX, int ntiles)
{
    constexpr int MROWS = MF * 32;
    constexpr int ABYTES = MROWS * 32;
    constexpr int SLICE  = 2 * ABYTES + 8192;
    constexpr int STAGE  = 2 * SLICE;
    constexpr int ACH    = MROWS * 2;
    constexpr int CPT    = (MROWS * 4 + 512) / 256;

    extern __shared__ char sm[];
    const uint32_t sb = smem_u32(sm);
    const int tid   = threadIdx.x;
    const int lane  = tid & 31;
    const int wid   = tid >> 5;
    const int wmB   = (wid >> 2) * (MF * 16);
    const int wnB   = (wid & 3) * 32;

    const int nst = K >> 5;

    int lrow[CPT], lch[CPT], larr[CPT];
    uint32_t lsw[CPT];
    #pragma unroll
    for (int i = 0; i < CPT; ++i) {
        int idx = tid + i * 256;
        if (idx < 2 * ACH) {
            larr[i] = idx / ACH;
            int w = idx % ACH;
            lrow[i] = w >> 1; lch[i] = w & 1;
            lsw[i]  = (uint32_t)larr[i] * ABYTES
                    + sw32((uint32_t)lrow[i] * 32u + (uint32_t)lch[i] * 16u);
        } else {
            int rem = idx - 2 * ACH;
            int bl  = rem >> 8;
            larr[i] = 2 + bl;
            int w = rem & 255;
            lrow[i] = w >> 1; lch[i] = w & 1;
            lsw[i]  = 2u * ABYTES + (uint32_t)bl * 4096u
                    + sw32((uint32_t)lrow[i] * 32u + (uint32_t)lch[i] * 16u);
        }
    }

    const uint32_t a_row = (uint32_t)(wmB + (lane & 15));
    const uint32_t a_cb  = (uint32_t)((lane >> 4) * 16);
    const uint32_t b_row = (uint32_t)(wnB + ((lane >> 4) & 1) * 8 + (lane & 7));
    const uint32_t b_cb  = (uint32_t)(((lane >> 3) & 1) * 16);

    for (int tile = blockIdx.x; tile < ntiles; tile += gridDim.x) {
        const int nBase = (tile % tilesX) * 128;
        const int mBase = (tile / tilesX) * MROWS;

        float acc[MF][4][4];
        #pragma unroll
        for (int a = 0; a < MF; ++a)
            #pragma unroll
            for (int b = 0; b < 4; ++b)
                #pragma unroll
                for (int c = 0; c < 4; ++c) acc[a][b][c] = 0.f;

        auto load_stage = [&](int stg, int s) {
            uint32_t base = sb + (uint32_t)stg * STAGE;
            #pragma unroll
            for (int q = 0; q < 2; ++q) {
                const size_t koff = (size_t)s * 32 + (size_t)q * 16;
                uint32_t sbase = base + (uint32_t)q * SLICE;
                #pragma unroll
                for (int i = 0; i < CPT; ++i) {
                    const __nv_bfloat16* src;
                    size_t goff;
                    if (larr[i] < 2) {
                        src  = (larr[i] == 0) ? Ahi : Alo;
                        goff = (size_t)(mBase + lrow[i]) * K + koff + (size_t)lch[i] * 8;
                    } else {
                        src  = (larr[i] == 2) ? Bhi : Blo;
                        goff = (size_t)(nBase + lrow[i]) * K + koff + (size_t)lch[i] * 8;
                    }
                    cpasync16(sbase + lsw[i], src + goff);
                }
            }
            asm volatile("cp.async.commit_group;" ::: "memory");
        };

        load_stage(0, 0);
        load_stage(1, 1);

        for (int s = 0; s < nst; ++s) {
            if (s < nst - 1) asm volatile("cp.async.wait_group 1;" ::: "memory");
            else             asm volatile("cp.async.wait_group 0;" ::: "memory");
            __syncthreads();

            const uint32_t stg = sb + (uint32_t)(s % NSTAGE) * STAGE;

            #pragma unroll
            for (int q = 0; q < 2; ++q) {
                const uint32_t sAhi = stg + (uint32_t)q * SLICE;
                const uint32_t sAlo = sAhi + ABYTES;
                const uint32_t sBhi = sAhi + 2 * ABYTES;
                const uint32_t sBlo = sBhi + 4096;

                uint32_t bh[4][2], bl[4][2];
                #pragma unroll
                for (int nf2 = 0; nf2 < 2; ++nf2) {
                    uint32_t off = sw32((b_row + (uint32_t)nf2 * 16u) * 32u + b_cb);
                    uint32_t r[4];
                    ldsm4(r, sBhi + off);
                    bh[nf2*2][0] = r[0]; bh[nf2*2][1] = r[1];
                    bh[nf2*2+1][0] = r[2]; bh[nf2*2+1][1] = r[3];
                    ldsm4(r, sBlo + off);
                    bl[nf2*2][0] = r[0]; bl[nf2*2][1] = r[1];
                    bl[nf2*2+1][0] = r[2]; bl[nf2*2+1][1] = r[3];
                }
                uint32_t ah[MF][4], al[MF][4];
                #pragma unroll
                for (int mf = 0; mf < MF; ++mf) {
                    uint32_t off = sw32((a_row + (uint32_t)mf * 16u) * 32u + a_cb);
                    ldsm4(ah[mf], sAhi + off);
                    ldsm4(al[mf], sAlo + off);
                }

                #pragma unroll
                for (int mf = 0; mf < MF; ++mf)
                    #pragma unroll
                    for (int nf = 0; nf < 4; ++nf)
                        mma16816(acc[mf][nf], ah[mf], bh[nf]);
                #pragma unroll
                for (int mf = 0; mf < MF; ++mf)
                    #pragma unroll
                    for (int nf = 0; nf < 4; ++nf)
                        mma16816(acc[mf][nf], ah[mf], bl[nf]);
                #pragma unroll
                for (int mf = 0; mf < MF; ++mf)
                    #pragma unroll
                    for (int nf = 0; nf < 4; ++nf)
                        mma16816(acc[mf][nf], al[mf], bh[nf]);
            }
            if (s + 2 < nst) load_stage((s + 2) % NSTAGE, s + 2);
        }

        const int gid = lane >> 2;
        const int tig = lane & 3;
        #pragma unroll
        for (int mf = 0; mf < MF; ++mf) {
            int row0 = mBase + wmB + mf * 16 + gid;
            #pragma unroll
            for (int nf = 0; nf < 4; ++nf) {
                int col = nBase + wnB + nf * 8 + tig * 2;
                if (col < Nreal) {
                    float2 v0 = make_float2(acc[mf][nf][0], acc[mf][nf][1]);
                    float2 v1 = make_float2(acc[mf][nf][2], acc[mf][nf][3]);
                    *(float2*)(C + (size_t)row0 * Nreal + col) = v0;
                    *(float2*)(C + (size_t)(row0 + 8) * Nreal + col) = v1;
                }
            }
        }
        __syncthreads();
    }
}

// ---------------- reset flags + ticket ----------------------------------------
__global__ void __launch_bounds__(256)
reset_kernel()
{
    int i = blockIdx.x * 256 + threadIdx.x;
    if (i < NBLK) g_flag[i] = 0;
    if (i == 0)   g_ticket = 0;
}

// ---------------- extract dtr columns of zx -> bf16 hi/lo ---------------------
__global__ void __launch_bounds__(256)
extract_dtr()
{
    int idx = blockIdx.x * 256 + threadIdx.x;       // 2048*64 = 131072
    if (idx >= L_SEQ * DT_RANK) return;
    int t = idx >> 6, k = idx & 63;
    float v = g_zx[(size_t)t * D_PROJ + OFF_DT + k];
    __nv_bfloat16 h = __float2bfloat16_rn(v);
    g_dtrhi[idx] = h;
    g_dtrlo[idx] = __float2bfloat16_rn(v - __bfloat162float(h));
}

// ---------------- dt post: softplus(pre + 2*bias) -----------------------------
__global__ void __launch_bounds__(256)
dt_post(const float* __restrict__ dt_bias)
{
    int i = (blockIdx.x * 256 + threadIdx.x) * 4;
    if (i >= L_SEQ * D_INNER) return;
    float4 v = *(const float4*)(g_P + i);
    int d = i & (D_INNER - 1);
    float o[4] = {v.x, v.y, v.z, v.w};
    #pragma unroll
    for (int t = 0; t < 4; ++t) {
        float s = o[t] + 2.f * dt_bias[d + t];
        o[t] = (s > 20.f) ? s : log1pf(__expf(s));
    }
    *(float4*)(g_delta + i) = make_float4(o[0], o[1], o[2], o[3]);
}

// ---------------- causal depthwise conv (K=4) + bias + silu -------------------
__global__ void __launch_bounds__(256)
conv_kernel(const float* __restrict__ w, const float* __restrict__ b)
{
    int idx = blockIdx.x * blockDim.x + threadIdx.x;
    if (idx >= L_SEQ * D_XB) return;
    int t = idx >> 9, c = idx & (D_XB - 1);
    float acc = b[c];
    #pragma unroll
    for (int k = 0; k < KCONV; ++k) {
        int tt = t - (KCONV - 1) + k;
        if (tt >= 0)
            acc = fmaf(w[c * KCONV + k], g_zx[(size_t)tt * D_PROJ + OFF_X + c], acc);
    }
    g_xconv[idx] = acc / (1.f + __expf(-acc));
}

// ---------------- fused scan: local scan + decoupled lookback + replay --------
__global__ void __launch_bounds__(256)
scan_fused(const float* __restrict__ A_log, const float* __restrict__ Dp)
{
    __shared__ int s_vid;
    __shared__ float s_dv[CH * 16], s_xv[CH * 16], s_B[CH * 16],
                     s_C [CH * 16], s_z [CH * 16];

    const int tid = threadIdx.x;
    if (tid == 0) s_vid = atomicAdd(&g_ticket, 1);
    __syncthreads();
    const int vid = s_vid;
    const int g   = vid >> 5;             // NCH = 32
    const int j   = vid & 31;
    const int p   = tid >> 4;
    const int n   = tid & 15;
    const int gx  = g >> 2;
    const int d   = g * D_STATE + p;

    const int i0 = tid >> 4, l = tid & 15;
    const int tbase = j * CH;
    #pragma unroll
    for (int r = 0; r < CH; r += 16) {
        int t = tbase + i0 + r;
        s_dv[(i0 + r) * 16 + l] = g_delta[(size_t)t * D_INNER + g * 16 + l];
        s_xv[(i0 + r) * 16 + l] = g_xconv[(size_t)t * D_XB + gx * 16 + l];
        s_B [(i0 + r) * 16 + l] = g_zx[(size_t)t * D_PROJ + OFF_B + gx * 16 + l];
        s_C [(i0 + r) * 16 + l] = g_zx[(size_t)t * D_PROJ + OFF_C + g * 16 + l];
        s_z [(i0 + r) * 16 + l] = g_zx[(size_t)t * D_PROJ + OFF_Z + g * 16 + l];
    }
    __syncthreads();

    const float A  = -expf(A_log[d * D_STATE + n]);
    const float Dv = Dp[d];

    // pass 1: local (P, E) from h = 0
    float h = 0.f, P = 1.f;
    #pragma unroll 8
    for (int i = 0; i < CH; ++i) {
        float dv = s_dv[i * 16 + p];
        float xv = s_xv[i * 16 + p];
        float Bv = s_B [i * 16 + n];
        float a  = __expf(dv * A);
        P *= a;
        h = fmaf(a, h, dv * xv * Bv);
    }

    // decoupled lookback: carry = final h of predecessor chunk
    float carry = 0.f;
    if (j > 0) {
        if (tid == 0)
            while (atomicAdd(&g_flag[vid - 1], 0) == 0) { }
        __syncthreads();
        carry = g_H[(size_t)(vid - 1) * 256 + tid];
    }
    float Hend = fmaf(P, carry, h);
    g_H[(size_t)vid * 256 + tid] = Hend;
    __threadfence();
    __syncthreads();
    if (tid == 0) atomicExch(&g_flag[vid], 1);

    // pass 2: replay with carry, C-reduce, gate, write bf16 hi/lo yg
    h = carry;
    #pragma unroll 4
    for (int i = 0; i < CH; ++i) {
        float dv = s_dv[i * 16 + p];
        float xv = s_xv[i * 16 + p];
        float Bv = s_B [i * 16 + n];
        float Cv = s_C [i * 16 + n];

        float a = __expf(dv * A);
        h = fmaf(a, h, dv * xv * Bv);

        float part = h * Cv;
        part += __shfl_xor_sync(0xffffffffu, part, 8);
        part += __shfl_xor_sync(0xffffffffu, part, 4);
        part += __shfl_xor_sync(0xffffffffu, part, 2);
        part += __shfl_xor_sync(0xffffffffu, part, 1);

        if (n == 0) {
            float zv = s_z[i * 16 + p];
            float sz = zv / (1.f + __expf(-zv));
            float yv = (part + Dv * xv) * sz;
            size_t oi = (size_t)(tbase + i) * D_INNER + d;
            __nv_bfloat16 hb = __float2bfloat16_rn(yv);
            g_ahi[oi] = hb;
            g_alo[oi] = __float2bfloat16_rn(yv - __bfloat162float(hb));
        }
    }
}

// ---------------- launch ------------------------------------------------------
extern "C" void kernel_launch(void* const* d_in, const int* in_sizes, int n_in,
                              void* d_out, int out_size)
{
    const float* hidden  = (const float*)d_in[0];
    const float* W_in    = (const float*)d_in[1];
    const float* conv_w  = (const float*)d_in[2];
    const float* conv_b  = (const float*)d_in[3];
    const float* W_dt    = (const float*)d_in[4];
    const float* dt_bias = (const float*)d_in[5];
    const float* A_log   = (const float*)d_in[6];
    const float* Dp      = (const float*)d_in[7];
    const float* W_out   = (const float*)d_in[8];
    float*       out     = (float*)d_out;

    const int SMEM1 = NSTAGE * 2 * (128 * 64 + 8192);  // MF=4: 96KB
    const int SMEM2 = NSTAGE * 2 * (64 * 64 + 8192);   // MF=2: 72KB
    cudaFuncSetAttribute(gemm_tc_kernel<4>,
                         cudaFuncAttributeMaxDynamicSharedMemorySize, SMEM1);
    cudaFuncSetAttribute(gemm_tc_kernel<2>,
                         cudaFuncAttributeMaxDynamicSharedMemorySize, SMEM2);

    float *zx, *dtpre;
    __nv_bfloat16 *ahi, *alo, *w1hi, *w1lo, *w2hi, *w2lo, *dtrhi, *dtrlo, *wdthi, *wdtlo;
    cudaGetSymbolAddress((void**)&zx,    g_zx);
    cudaGetSymbolAddress((void**)&dtpre, g_P);
    cudaGetSymbolAddress((void**)&ahi,   g_ahi);
    cudaGetSymbolAddress((void**)&alo,   g_alo);
    cudaGetSymbolAddress((void**)&w1hi,  g_w1hi);
    cudaGetSymbolAddress((void**)&w1lo,  g_w1lo);
    cudaGetSymbolAddress((void**)&w2hi,  g_w2hi);
    cudaGetSymbolAddress((void**)&w2lo,  g_w2lo);
    cudaGetSymbolAddress((void**)&dtrhi, g_dtrhi);
    cudaGetSymbolAddress((void**)&dtrlo, g_dtrlo);
    cudaGetSymbolAddress((void**)&wdthi, g_wdthi);
    cudaGetSymbolAddress((void**)&wdtlo, g_wdtlo);

    // 1-3) operand prep (GEMM1 stays in profiled slot 4)
    transpose_wt<<<dim3(NPAD1 / 32, D_MODEL / 32), 256>>>(W_in, w1hi, w1lo, D_MODEL, D_PROJ);
    transpose_wt<<<dim3(D_MODEL / 32, D_INNER / 32), 256>>>(W_out, w2hi, w2lo, D_INNER, D_MODEL);
    convert_hilo<<<(L_SEQ * D_MODEL) / 1024, 256>>>(hidden, ahi, alo, L_SEQ * D_MODEL);

    // 4) zxbcdt = hidden @ W_in — 128x128 tiles, 592 persistent workers
    {
        int tilesX = NPAD1 / 128;                   // 41
        int ntiles = tilesX * (L_SEQ / 128);        // 656
        gemm_tc_kernel<4><<<592, 256, SMEM1>>>(
            ahi, alo, w1hi, w1lo, zx, D_PROJ, D_MODEL, tilesX, ntiles);
    }

    // 5) reset lookback state (needed fresh every graph replay)
    reset_kernel<<<(NBLK + 255) / 256, 256>>>();

    // 6-9) dt path via tensor cores: extract dtr, transpose W_dt, GEMM K=64, softplus
    transpose_wt<<<dim3(D_INNER / 32, DT_RANK / 32), 256>>>(W_dt, wdthi, wdtlo, DT_RANK, D_INNER);
    extract_dtr<<<(L_SEQ * DT_RANK) / 256, 256>>>();
    {
        int tilesX = D_INNER / 128;                 // 16
        int ntiles = tilesX * (L_SEQ / 128);        // 256
        gemm_tc_kernel<4><<<256, 256, SMEM1>>>(
            dtrhi, dtrlo, wdthi, wdtlo, dtpre, D_INNER, DT_RANK, tilesX, ntiles);
    }
    dt_post<<<(L_SEQ * D_INNER) / 1024, 256>>>(dt_bias);

    // 10) conv + silu
    conv_kernel<<<(L_SEQ * D_XB + 255) / 256, 256>>>(conv_w, conv_b);

    // 11) fused scan (writes bf16 hi/lo yg into g_ahi/g_alo)
    scan_fused<<<NBLK, 256>>>(A_log, Dp);

    // 12) out = yg @ W_out — 64x128 tiles, 256 CTAs, single wave
    {
        int tilesX = D_MODEL / 128;                 // 8
        int ntiles = tilesX * (L_SEQ / 64);         // 256
        gemm_tc_kernel<2><<<256, 256, SMEM2>>>(
            ahi, alo, w2hi, w2lo, out, D_MODEL, D_INNER, tilesX, ntiles);
    }
}

// round 13
// speedup vs baseline: 1.1759x; 1.1759x over previous
#include <cuda_runtime.h>
#include <cuda_bf16.h>
#include <cstdint>

// ---------------- problem constants ----------------
#define L_SEQ    2048
#define D_MODEL  1024
#define D_INNER  2048
#define D_XB     512
#define D_STATE  16
#define DT_RANK  64
#define KCONV    4
#define G_HEADS  128
#define GX_HEADS 32
#define D_PROJ   5184
#define NPAD1    5248          // D_PROJ padded to multiple of 128

#define OFF_Z    0
#define OFF_X    2048
#define OFF_B    2560
#define OFF_C    3072
#define OFF_DT   5120

// scan chunking
#define CH       64
#define NCH      32            // L_SEQ / CH

// ---------------- scratch (static device globals; no runtime allocation) ----
__device__ float g_zx   [L_SEQ * D_PROJ];
__device__ float g_delta[L_SEQ * D_INNER];
__device__ float g_xconv[L_SEQ * D_XB];
__device__ float g_part [L_SEQ * D_MODEL];     // GEMM2 k-split partial

__device__ float g_cP [NCH * G_HEADS * 256];
__device__ float g_cE [NCH * G_HEADS * 256];
__device__ float g_cC [NCH * G_HEADS * 256];

__device__ __nv_bfloat16 g_ahi [L_SEQ * D_INNER];
__device__ __nv_bfloat16 g_alo [L_SEQ * D_INNER];
__device__ __nv_bfloat16 g_w1hi[NPAD1 * D_MODEL];
__device__ __nv_bfloat16 g_w1lo[NPAD1 * D_MODEL];
__device__ __nv_bfloat16 g_w2hi[D_MODEL * D_INNER];
__device__ __nv_bfloat16 g_w2lo[D_MODEL * D_INNER];

// ================= low-level helpers =========================================
__device__ __forceinline__ uint32_t smem_u32(const void* p) {
    return (uint32_t)__cvta_generic_to_shared(p);
}
__device__ __forceinline__ void cpasync16(uint32_t saddr, const void* g) {
    asm volatile("cp.async.cg.shared.global [%0], [%1], 16;" :: "r"(saddr), "l"(g));
}
__device__ __forceinline__ void ldsm4(uint32_t* r, uint32_t addr) {
    asm volatile("ldmatrix.sync.aligned.m8n8.x4.shared.b16 {%0,%1,%2,%3}, [%4];"
        : "=r"(r[0]), "=r"(r[1]), "=r"(r[2]), "=r"(r[3]) : "r"(addr));
}
__device__ __forceinline__ void mma16816(float* d, const uint32_t* a, const uint32_t* b) {
    asm volatile("mma.sync.aligned.m16n8k16.row.col.f32.bf16.bf16.f32 "
        "{%0,%1,%2,%3}, {%4,%5,%6,%7}, {%8,%9}, {%0,%1,%2,%3};"
        : "+f"(d[0]), "+f"(d[1]), "+f"(d[2]), "+f"(d[3])
        : "r"(a[0]), "r"(a[1]), "r"(a[2]), "r"(a[3]), "r"(b[0]), "r"(b[1]));
}
__device__ __forceinline__ uint32_t sw32(uint32_t off) {
    return off ^ ((off >> 3) & 0x70);
}

// ================= fp32 -> bf16 hi/lo conversion =============================
__global__ void __launch_bounds__(256)
convert_hilo(const float* __restrict__ in, __nv_bfloat16* __restrict__ hi,
             __nv_bfloat16* __restrict__ lo, int count)
{
    int i = (blockIdx.x * 256 + threadIdx.x) * 4;
    if (i >= count) return;
    float4 v = *(const float4*)(in + i);
    float vv[4] = {v.x, v.y, v.z, v.w};
    __nv_bfloat16 h[4], l[4];
    #pragma unroll
    for (int j = 0; j < 4; ++j) {
        h[j] = __float2bfloat16_rn(vv[j]);
        l[j] = __float2bfloat16_rn(vv[j] - __bfloat162float(h[j]));
    }
    *(uint2*)(hi + i) = *(uint2*)h;
    *(uint2*)(lo + i) = *(uint2*)l;
}

// ================= transpose W [K,N] -> [Npad,K] bf16 hi/lo ==================
__global__ void __launch_bounds__(256)
transpose_wt(const float* __restrict__ W, __nv_bfloat16* __restrict__ Thi,
             __nv_bfloat16* __restrict__ Tlo, int K, int N)
{
    __shared__ float tile[32][33];
    int n0 = blockIdx.x * 32;
    int k0 = blockIdx.y * 32;
    int tx = threadIdx.x & 31, ty = threadIdx.x >> 5;
    #pragma unroll
    for (int r = 0; r < 4; ++r) {
        int k = k0 + ty + r * 8;
        int n = n0 + tx;
        tile[ty + r * 8][tx] = (n < N) ? W[(size_t)k * N + n] : 0.f;
    }
    __syncthreads();
    #pragma unroll
    for (int r = 0; r < 4; ++r) {
        int n = n0 + ty + r * 8;
        int k = k0 + tx;
        float v = tile[tx][ty + r * 8];
        __nv_bfloat16 h = __float2bfloat16_rn(v);
        Thi[(size_t)n * K + k] = h;
        Tlo[(size_t)n * K + k] = __float2bfloat16_rn(v - __bfloat162float(h));
    }
}

// ================= split-bf16 warp-MMA GEMM (persistent + optional K-split) ==
// CTA tile 128x128 (MF=4), 8 warps (2m x 4n), warp tile 64x32.
// Pipeline stage = TWO k=16 slices; 3 stages; exact tail waits.
// K-split: tiles [0, ntHalf) compute K-range [0,Kiter) into C;
//          tiles [ntHalf, ntiles) compute K-range [Kiter, 2*Kiter) into C2.
#define NSTAGE   3
#define MF       4
#define MROWS    (MF * 32)
#define ABYTES   (MROWS * 32)
#define SLICE    (2 * ABYTES + 8192)
#define STAGE    (2 * SLICE)
#define GEMM_SMEM (NSTAGE * STAGE)     // 96KB

__global__ void __launch_bounds__(256, 2)
gemm_tc_kernel(const __nv_bfloat16* __restrict__ Ahi, const __nv_bfloat16* __restrict__ Alo,
               const __nv_bfloat16* __restrict__ Bhi, const __nv_bfloat16* __restrict__ Blo,
               float* __restrict__ C, float* __restrict__ C2,
               int Nreal, int Kiter, int ld, int tilesX, int ntiles, int ntHalf)
{
    constexpr int ACH = MROWS * 2;
    constexpr int CPT = (MROWS * 4 + 512) / 256;

    extern __shared__ char sm[];
    const uint32_t sb = smem_u32(sm);
    const int tid   = threadIdx.x;
    const int lane  = tid & 31;
    const int wid   = tid >> 5;
    const int wmB   = (wid >> 2) * (MF * 16);
    const int wnB   = (wid & 3) * 32;

    const int nst = Kiter >> 5;

    int lrow[CPT], lch[CPT], larr[CPT];
    uint32_t lsw[CPT];
    #pragma unroll
    for (int i = 0; i < CPT; ++i) {
        int idx = tid + i * 256;
        if (idx < 2 * ACH) {
            larr[i] = idx / ACH;
            int w = idx % ACH;
            lrow[i] = w >> 1; lch[i] = w & 1;
            lsw[i]  = (uint32_t)larr[i] * ABYTES
                    + sw32((uint32_t)lrow[i] * 32u + (uint32_t)lch[i] * 16u);
        } else {
            int rem = idx - 2 * ACH;
            int bl  = rem >> 8;
            larr[i] = 2 + bl;
            int w = rem & 255;
            lrow[i] = w >> 1; lch[i] = w & 1;
            lsw[i]  = 2u * ABYTES + (uint32_t)bl * 4096u
                    + sw32((uint32_t)lrow[i] * 32u + (uint32_t)lch[i] * 16u);
        }
    }

    const uint32_t a_row = (uint32_t)(wmB + (lane & 15));
    const uint32_t a_cb  = (uint32_t)((lane >> 4) * 16);
    const uint32_t b_row = (uint32_t)(wnB + ((lane >> 4) & 1) * 8 + (lane & 7));
    const uint32_t b_cb  = (uint32_t)(((lane >> 3) & 1) * 16);

    for (int tile = blockIdx.x; tile < ntiles; tile += gridDim.x) {
        int t2 = tile;
        float* Cw = C;
        size_t kbase = 0;
        if (tile >= ntHalf) {               // K-split second half
            t2 = tile - ntHalf;
            Cw = C2;
            kbase = (size_t)Kiter;
        }
        const int nBase = (t2 % tilesX) * 128;
        const int mBase = (t2 / tilesX) * MROWS;

        float acc[MF][4][4];
        #pragma unroll
        for (int a = 0; a < MF; ++a)
            #pragma unroll
            for (int b = 0; b < 4; ++b)
                #pragma unroll
                for (int c = 0; c < 4; ++c) acc[a][b][c] = 0.f;

        auto load_stage = [&](int stg, int s) {
            uint32_t base = sb + (uint32_t)stg * STAGE;
            #pragma unroll
            for (int q = 0; q < 2; ++q) {
                const size_t koff = kbase + (size_t)s * 32 + (size_t)q * 16;
                uint32_t sbase = base + (uint32_t)q * SLICE;
                #pragma unroll
                for (int i = 0; i < CPT; ++i) {
                    const __nv_bfloat16* src;
                    size_t goff;
                    if (larr[i] < 2) {
                        src  = (larr[i] == 0) ? Ahi : Alo;
                        goff = (size_t)(mBase + lrow[i]) * ld + koff + (size_t)lch[i] * 8;
                    } else {
                        src  = (larr[i] == 2) ? Bhi : Blo;
                        goff = (size_t)(nBase + lrow[i]) * ld + koff + (size_t)lch[i] * 8;
                    }
                    cpasync16(sbase + lsw[i], src + goff);
                }
            }
            asm volatile("cp.async.commit_group;" ::: "memory");
        };

        load_stage(0, 0);
        load_stage(1, 1);

        for (int s = 0; s < nst; ++s) {
            if (s < nst - 1) asm volatile("cp.async.wait_group 1;" ::: "memory");
            else             asm volatile("cp.async.wait_group 0;" ::: "memory");
            __syncthreads();

            const uint32_t stg = sb + (uint32_t)(s % NSTAGE) * STAGE;

            #pragma unroll
            for (int q = 0; q < 2; ++q) {
                const uint32_t sAhi = stg + (uint32_t)q * SLICE;
                const uint32_t sAlo = sAhi + ABYTES;
                const uint32_t sBhi = sAhi + 2 * ABYTES;
                const uint32_t sBlo = sBhi + 4096;

                uint32_t bh[4][2], bl[4][2];
                #pragma unroll
                for (int nf2 = 0; nf2 < 2; ++nf2) {
                    uint32_t off = sw32((b_row + (uint32_t)nf2 * 16u) * 32u + b_cb);
                    uint32_t r[4];
                    ldsm4(r, sBhi + off);
                    bh[nf2*2][0] = r[0]; bh[nf2*2][1] = r[1];
                    bh[nf2*2+1][0] = r[2]; bh[nf2*2+1][1] = r[3];
                    ldsm4(r, sBlo + off);
                    bl[nf2*2][0] = r[0]; bl[nf2*2][1] = r[1];
                    bl[nf2*2+1][0] = r[2]; bl[nf2*2+1][1] = r[3];
                }
                uint32_t ah[MF][4], al[MF][4];
                #pragma unroll
                for (int mf = 0; mf < MF; ++mf) {
                    uint32_t off = sw32((a_row + (uint32_t)mf * 16u) * 32u + a_cb);
                    ldsm4(ah[mf], sAhi + off);
                    ldsm4(al[mf], sAlo + off);
                }

                #pragma unroll
                for (int mf = 0; mf < MF; ++mf)
                    #pragma unroll
                    for (int nf = 0; nf < 4; ++nf)
                        mma16816(acc[mf][nf], ah[mf], bh[nf]);
                #pragma unroll
                for (int mf = 0; mf < MF; ++mf)
                    #pragma unroll
                    for (int nf = 0; nf < 4; ++nf)
                        mma16816(acc[mf][nf], ah[mf], bl[nf]);
                #pragma unroll
                for (int mf = 0; mf < MF; ++mf)
                    #pragma unroll
                    for (int nf = 0; nf < 4; ++nf)
                        mma16816(acc[mf][nf], al[mf], bh[nf]);
            }
            if (s + 2 < nst) load_stage((s + 2) % NSTAGE, s + 2);
        }

        const int gid = lane >> 2;
        const int tig = lane & 3;
        #pragma unroll
        for (int mf = 0; mf < MF; ++mf) {
            int row0 = mBase + wmB + mf * 16 + gid;
            #pragma unroll
            for (int nf = 0; nf < 4; ++nf) {
                int col = nBase + wnB + nf * 8 + tig * 2;
                if (col < Nreal) {
                    float2 v0 = make_float2(acc[mf][nf][0], acc[mf][nf][1]);
                    float2 v1 = make_float2(acc[mf][nf][2], acc[mf][nf][3]);
                    *(float2*)(Cw + (size_t)row0 * Nreal + col) = v0;
                    *(float2*)(Cw + (size_t)(row0 + 8) * Nreal + col) = v1;
                }
            }
        }
        __syncthreads();
    }
}

// ---------------- add partial: out += part -----------------------------------
__global__ void __launch_bounds__(256)
add_partial(float* __restrict__ out, const float* __restrict__ part, int count)
{
    int i = (blockIdx.x * 256 + threadIdx.x) * 4;
    if (i >= count) return;
    float4 a = *(const float4*)(out + i);
    float4 b = *(const float4*)(part + i);
    *(float4*)(out + i) = make_float4(a.x + b.x, a.y + b.y, a.z + b.z, a.w + b.w);
}

// ---------------- dt projection + softplus ------------------------------------
__global__ void __launch_bounds__(256)
dt_kernel(const float* __restrict__ W_dt, const float* __restrict__ dt_bias)
{
    __shared__ float s_r[64 * DT_RANK];
    const int t0 = blockIdx.x * 64;
    const int d  = blockIdx.y * 256 + threadIdx.x;

    #pragma unroll
    for (int k = 0; k < 16; ++k) {
        int idx = threadIdx.x + k * 256;
        int row = idx >> 6, col = idx & 63;
        s_r[idx] = g_zx[(size_t)(t0 + row) * D_PROJ + OFF_DT + col];
    }
    __syncthreads();

    float w[DT_RANK];
    #pragma unroll
    for (int k = 0; k < DT_RANK; ++k)
        w[k] = W_dt[(size_t)k * D_INNER + d];

    const float bias2 = 2.f * dt_bias[d];

    for (int tt = 0; tt < 64; ++tt) {
        const float4* rp = (const float4*)(s_r + tt * DT_RANK);
        float s = bias2;
        #pragma unroll
        for (int k4 = 0; k4 < DT_RANK / 4; ++k4) {
            float4 r4 = rp[k4];
            s = fmaf(r4.x, w[k4*4+0], s);
            s = fmaf(r4.y, w[k4*4+1], s);
            s = fmaf(r4.z, w[k4*4+2], s);
            s = fmaf(r4.w, w[k4*4+3], s);
        }
        float sp = (s > 20.f) ? s : log1pf(__expf(s));
        g_delta[(size_t)(t0 + tt) * D_INNER + d] = sp;
    }
}

// ---------------- causal depthwise conv (K=4) + bias + silu -------------------
__global__ void __launch_bounds__(256)
conv_kernel(const float* __restrict__ w, const float* __restrict__ b)
{
    int idx = blockIdx.x * blockDim.x + threadIdx.x;
    if (idx >= L_SEQ * D_XB) return;
    int t = idx >> 9, c = idx & (D_XB - 1);
    float acc = b[c];
    #pragma unroll
    for (int k = 0; k < KCONV; ++k) {
        int tt = t - (KCONV - 1) + k;
        if (tt >= 0)
            acc = fmaf(w[c * KCONV + k], g_zx[(size_t)tt * D_PROJ + OFF_X + c], acc);
    }
    g_xconv[idx] = acc / (1.f + __expf(-acc));
}

// ---------------- chunked selective scan (R5 3-phase) --------------------------
__global__ void __launch_bounds__(256)
scan_phase_a(const float* __restrict__ A_log)
{
    const int g   = blockIdx.x;
    const int j   = blockIdx.y;
    const int tid = threadIdx.x;
    const int p   = tid >> 4;
    const int n   = tid & 15;
    const int gx  = g >> 2;
    const int d   = g * D_STATE + p;

    __shared__ float s_dv[CH * 16], s_xv[CH * 16], s_B[CH * 16];

    const int i0 = tid >> 4, l = tid & 15;
    const int tbase = j * CH;
    #pragma unroll
    for (int r = 0; r < CH; r += 16) {
        int t = tbase + i0 + r;
        s_dv[(i0 + r) * 16 + l] = g_delta[(size_t)t * D_INNER + g * 16 + l];
        s_xv[(i0 + r) * 16 + l] = g_xconv[(size_t)t * D_XB + gx * 16 + l];
        s_B [(i0 + r) * 16 + l] = g_zx[(size_t)t * D_PROJ + OFF_B + gx * 16 + l];
    }
    __syncthreads();

    const float A = -expf(A_log[d * D_STATE + n]);
    float h = 0.f, P = 1.f;
    #pragma unroll 8
    for (int i = 0; i < CH; ++i) {
        float dv = s_dv[i * 16 + p];
        float xv = s_xv[i * 16 + p];
        float Bv = s_B [i * 16 + n];
        float a  = __expf(dv * A);
        P *= a;
        h = fmaf(a, h, dv * xv * Bv);
    }
    int idx = (j * G_HEADS + g) * 256 + tid;
    g_cP[idx] = P;
    g_cE[idx] = h;
}

__global__ void __launch_bounds__(256)
scan_phase_b()
{
    const int g   = blockIdx.x;
    const int tid = threadIdx.x;
    float c = 0.f;
    #pragma unroll
    for (int j = 0; j < NCH; ++j) {
        int idx = (j * G_HEADS + g) * 256 + tid;
        float P = g_cP[idx];
        float E = g_cE[idx];
        g_cC[idx] = c;
        c = fmaf(P, c, E);
    }
}

__global__ void __launch_bounds__(256)
scan_phase_c(const float* __restrict__ A_log, const float* __restrict__ Dp)
{
    const int g   = blockIdx.x;
    const int j   = blockIdx.y;
    const int tid = threadIdx.x;
    const int p   = tid >> 4;
    const int n   = tid & 15;
    const int gx  = g >> 2;
    const int d   = g * D_STATE + p;

    __shared__ float s_dv[CH * 16], s_xv[CH * 16], s_B[CH * 16],
                     s_C [CH * 16], s_z [CH * 16];

    const int i0 = tid >> 4, l = tid & 15;
    const int tbase = j * CH;
    #pragma unroll
    for (int r = 0; r < CH; r += 16) {
        int t = tbase + i0 + r;
        s_dv[(i0 + r) * 16 + l] = g_delta[(size_t)t * D_INNER + g * 16 + l];
        s_xv[(i0 + r) * 16 + l] = g_xconv[(size_t)t * D_XB + gx * 16 + l];
        s_B [(i0 + r) * 16 + l] = g_zx[(size_t)t * D_PROJ + OFF_B + gx * 16 + l];
        s_C [(i0 + r) * 16 + l] = g_zx[(size_t)t * D_PROJ + OFF_C + g * 16 + l];
        s_z [(i0 + r) * 16 + l] = g_zx[(size_t)t * D_PROJ + OFF_Z + g * 16 + l];
    }
    __syncthreads();

    const float A  = -expf(A_log[d * D_STATE + n]);
    const float Dv = Dp[d];
    float h = g_cC[(j * G_HEADS + g) * 256 + tid];

    #pragma unroll 4
    for (int i = 0; i < CH; ++i) {
        float dv = s_dv[i * 16 + p];
        float xv = s_xv[i * 16 + p];
        float Bv = s_B [i * 16 + n];
        float Cv = s_C [i * 16 + n];

        float a = __expf(dv * A);
        h = fmaf(a, h, dv * xv * Bv);

        float part = h * Cv;
        part += __shfl_xor_sync(0xffffffffu, part, 8);
        part += __shfl_xor_sync(0xffffffffu, part, 4);
        part += __shfl_xor_sync(0xffffffffu, part, 2);
        part += __shfl_xor_sync(0xffffffffu, part, 1);

        if (n == 0) {
            float zv = s_z[i * 16 + p];
            float sz = zv / (1.f + __expf(-zv));
            float yv = (part + Dv * xv) * sz;
            size_t oi = (size_t)(tbase + i) * D_INNER + d;
            __nv_bfloat16 hb = __float2bfloat16_rn(yv);
            g_ahi[oi] = hb;
            g_alo[oi] = __float2bfloat16_rn(yv - __bfloat162float(hb));
        }
    }
}

// ---------------- launch ------------------------------------------------------
extern "C" void kernel_launch(void* const* d_in, const int* in_sizes, int n_in,
                              void* d_out, int out_size)
{
    const float* hidden  = (const float*)d_in[0];
    const float* W_in    = (const float*)d_in[1];
    const float* conv_w  = (const float*)d_in[2];
    const float* conv_b  = (const float*)d_in[3];
    const float* W_dt    = (const float*)d_in[4];
    const float* dt_bias = (const float*)d_in[5];
    const float* A_log   = (const float*)d_in[6];
    const float* Dp      = (const float*)d_in[7];
    const float* W_out   = (const float*)d_in[8];
    float*       out     = (float*)d_out;

    cudaFuncSetAttribute(gemm_tc_kernel,
                         cudaFuncAttributeMaxDynamicSharedMemorySize, GEMM_SMEM);

    float *zx, *gpart;
    __nv_bfloat16 *ahi, *alo, *w1hi, *w1lo, *w2hi, *w2lo;
    cudaGetSymbolAddress((void**)&zx,    g_zx);
    cudaGetSymbolAddress((void**)&gpart, g_part);
    cudaGetSymbolAddress((void**)&ahi,   g_ahi);
    cudaGetSymbolAddress((void**)&alo,   g_alo);
    cudaGetSymbolAddress((void**)&w1hi,  g_w1hi);
    cudaGetSymbolAddress((void**)&w1lo,  g_w1lo);
    cudaGetSymbolAddress((void**)&w2hi,  g_w2hi);
    cudaGetSymbolAddress((void**)&w2lo,  g_w2lo);

    // 1-3) operand prep (GEMM1 in profiled slot 4)
    transpose_wt<<<dim3(NPAD1 / 32, D_MODEL / 32), 256>>>(W_in, w1hi, w1lo, D_MODEL, D_PROJ);
    transpose_wt<<<dim3(D_MODEL / 32, D_INNER / 32), 256>>>(W_out, w2hi, w2lo, D_INNER, D_MODEL);
    convert_hilo<<<(L_SEQ * D_MODEL) / 1024, 256>>>(hidden, ahi, alo, L_SEQ * D_MODEL);

    // 4) zxbcdt = hidden @ W_in — 128x128 tiles, 592 persistent workers
    {
        int tilesX = NPAD1 / 128;                   // 41
        int ntiles = tilesX * (L_SEQ / 128);        // 656
        gemm_tc_kernel<<<592, 256, GEMM_SMEM>>>(
            ahi, alo, w1hi, w1lo, zx, zx,
            D_PROJ, D_MODEL, D_MODEL, tilesX, ntiles, ntiles);
    }

    // 5-6) delta + conv
    dt_kernel<<<dim3(L_SEQ / 64, D_INNER / 256), 256>>>(W_dt, dt_bias);
    conv_kernel<<<(L_SEQ * D_XB + 255) / 256, 256>>>(conv_w, conv_b);

    // 7-9) chunked scan (phase C writes bf16 hi/lo yg into g_ahi/g_alo)
    scan_phase_a<<<dim3(G_HEADS, NCH), 256>>>(A_log);
    scan_phase_b<<<G_HEADS, 256>>>();
    scan_phase_c<<<dim3(G_HEADS, NCH), 256>>>(A_log, Dp);

    // 10) out = yg @ W_out — K-split: 256 CTAs coresident (full chip),
    //     half 0 (K 0..1023) -> out, half 1 (K 1024..2047) -> g_part
    {
        int tilesX = D_MODEL / 128;                 // 8
        int ntHalf = tilesX * (L_SEQ / 128);        // 128
        gemm_tc_kernel<<<256, 256, GEMM_SMEM>>>(
            ahi, alo, w2hi, w2lo, out, gpart,
            D_MODEL, D_INNER / 2, D_INNER, tilesX, 2 * ntHalf, ntHalf);
    }
    // 11) out += partial
    add_partial<<<(L_SEQ * D_MODEL) / 1024, 256>>>(out, gpart, L_SEQ * D_MODEL);
}

// round 14
// speedup vs baseline: 1.2982x; 1.1040x over previous
#include <cuda_runtime.h>
#include <cuda_bf16.h>
#include <cstdint>

// ---------------- problem constants ----------------
#define L_SEQ    2048
#define D_MODEL  1024
#define D_INNER  2048
#define D_XB     512
#define D_STATE  16
#define DT_RANK  64
#define KCONV    4
#define G_HEADS  128
#define GX_HEADS 32
#define D_PROJ   5184
#define NPAD1    5248          // D_PROJ padded to multiple of 128

#define OFF_Z    0
#define OFF_X    2048
#define OFF_B    2560
#define OFF_C    3072
#define OFF_DT   5120

// scan chunking: 32 timesteps per chunk, 64 chunks
#define CH       32
#define NCH      64

// ---------------- scratch (static device globals; no runtime allocation) ----
__device__ float g_zx   [L_SEQ * D_PROJ];
__device__ float g_delta[L_SEQ * D_INNER];
__device__ float g_xconv[L_SEQ * D_XB];
__device__ float g_part [L_SEQ * D_MODEL];     // GEMM2 k-split partial

// scan carries: [NCH][D_INNER*16] = (chunk, d, n)
__device__ float g_cP [NCH * D_INNER * D_STATE];
__device__ float g_cE [NCH * D_INNER * D_STATE];
__device__ float g_cC [NCH * D_INNER * D_STATE];

__device__ __nv_bfloat16 g_ahi [L_SEQ * D_INNER];
__device__ __nv_bfloat16 g_alo [L_SEQ * D_INNER];
__device__ __nv_bfloat16 g_w1hi[NPAD1 * D_MODEL];
__device__ __nv_bfloat16 g_w1lo[NPAD1 * D_MODEL];
__device__ __nv_bfloat16 g_w2hi[D_MODEL * D_INNER];
__device__ __nv_bfloat16 g_w2lo[D_MODEL * D_INNER];

// ================= low-level helpers =========================================
__device__ __forceinline__ uint32_t smem_u32(const void* p) {
    return (uint32_t)__cvta_generic_to_shared(p);
}
__device__ __forceinline__ void cpasync16(uint32_t saddr, const void* g) {
    asm volatile("cp.async.cg.shared.global [%0], [%1], 16;" :: "r"(saddr), "l"(g));
}
__device__ __forceinline__ void ldsm4(uint32_t* r, uint32_t addr) {
    asm volatile("ldmatrix.sync.aligned.m8n8.x4.shared.b16 {%0,%1,%2,%3}, [%4];"
        : "=r"(r[0]), "=r"(r[1]), "=r"(r[2]), "=r"(r[3]) : "r"(addr));
}
__device__ __forceinline__ void mma16816(float* d, const uint32_t* a, const uint32_t* b) {
    asm volatile("mma.sync.aligned.m16n8k16.row.col.f32.bf16.bf16.f32 "
        "{%0,%1,%2,%3}, {%4,%5,%6,%7}, {%8,%9}, {%0,%1,%2,%3};"
        : "+f"(d[0]), "+f"(d[1]), "+f"(d[2]), "+f"(d[3])
        : "r"(a[0]), "r"(a[1]), "r"(a[2]), "r"(a[3]), "r"(b[0]), "r"(b[1]));
}
__device__ __forceinline__ uint32_t sw32(uint32_t off) {
    return off ^ ((off >> 3) & 0x70);
}

// ================= fp32 -> bf16 hi/lo conversion =============================
__global__ void __launch_bounds__(256)
convert_hilo(const float* __restrict__ in, __nv_bfloat16* __restrict__ hi,
             __nv_bfloat16* __restrict__ lo, int count)
{
    int i = (blockIdx.x * 256 + threadIdx.x) * 4;
    if (i >= count) return;
    float4 v = *(const float4*)(in + i);
    float vv[4] = {v.x, v.y, v.z, v.w};
    __nv_bfloat16 h[4], l[4];
    #pragma unroll
    for (int j = 0; j < 4; ++j) {
        h[j] = __float2bfloat16_rn(vv[j]);
        l[j] = __float2bfloat16_rn(vv[j] - __bfloat162float(h[j]));
    }
    *(uint2*)(hi + i) = *(uint2*)h;
    *(uint2*)(lo + i) = *(uint2*)l;
}

// ================= transpose W [K,N] -> [Npad,K] bf16 hi/lo ==================
__global__ void __launch_bounds__(256)
transpose_wt(const float* __restrict__ W, __nv_bfloat16* __restrict__ Thi,
             __nv_bfloat16* __restrict__ Tlo, int K, int N)
{
    __shared__ float tile[32][33];
    int n0 = blockIdx.x * 32;
    int k0 = blockIdx.y * 32;
    int tx = threadIdx.x & 31, ty = threadIdx.x >> 5;
    #pragma unroll
    for (int r = 0; r < 4; ++r) {
        int k = k0 + ty + r * 8;
        int n = n0 + tx;
        tile[ty + r * 8][tx] = (n < N) ? W[(size_t)k * N + n] : 0.f;
    }
    __syncthreads();
    #pragma unroll
    for (int r = 0; r < 4; ++r) {
        int n = n0 + ty + r * 8;
        int k = k0 + tx;
        float v = tile[tx][ty + r * 8];
        __nv_bfloat16 h = __float2bfloat16_rn(v);
        Thi[(size_t)n * K + k] = h;
        Tlo[(size_t)n * K + k] = __float2bfloat16_rn(v - __bfloat162float(h));
    }
}

// ================= split-bf16 warp-MMA GEMM (persistent + optional K-split) ==
#define NSTAGE   3
#define MF       4
#define MROWS    (MF * 32)
#define ABYTES   (MROWS * 32)
#define SLICE    (2 * ABYTES + 8192)
#define STAGE    (2 * SLICE)
#define GEMM_SMEM (NSTAGE * STAGE)     // 96KB

__global__ void __launch_bounds__(256, 2)
gemm_tc_kernel(const __nv_bfloat16* __restrict__ Ahi, const __nv_bfloat16* __restrict__ Alo,
               const __nv_bfloat16* __restrict__ Bhi, const __nv_bfloat16* __restrict__ Blo,
               float* __restrict__ C, float* __restrict__ C2,
               int Nreal, int Kiter, int ld, int tilesX, int ntiles, int ntHalf)
{
    constexpr int ACH = MROWS * 2;
    constexpr int CPT = (MROWS * 4 + 512) / 256;

    extern __shared__ char sm[];
    const uint32_t sb = smem_u32(sm);
    const int tid   = threadIdx.x;
    const int lane  = tid & 31;
    const int wid   = tid >> 5;
    const int wmB   = (wid >> 2) * (MF * 16);
    const int wnB   = (wid & 3) * 32;

    const int nst = Kiter >> 5;

    int lrow[CPT], lch[CPT], larr[CPT];
    uint32_t lsw[CPT];
    #pragma unroll
    for (int i = 0; i < CPT; ++i) {
        int idx = tid + i * 256;
        if (idx < 2 * ACH) {
            larr[i] = idx / ACH;
            int w = idx % ACH;
            lrow[i] = w >> 1; lch[i] = w & 1;
            lsw[i]  = (uint32_t)larr[i] * ABYTES
                    + sw32((uint32_t)lrow[i] * 32u + (uint32_t)lch[i] * 16u);
        } else {
            int rem = idx - 2 * ACH;
            int bl  = rem >> 8;
            larr[i] = 2 + bl;
            int w = rem & 255;
            lrow[i] = w >> 1; lch[i] = w & 1;
            lsw[i]  = 2u * ABYTES + (uint32_t)bl * 4096u
                    + sw32((uint32_t)lrow[i] * 32u + (uint32_t)lch[i] * 16u);
        }
    }

    const uint32_t a_row = (uint32_t)(wmB + (lane & 15));
    const uint32_t a_cb  = (uint32_t)((lane >> 4) * 16);
    const uint32_t b_row = (uint32_t)(wnB + ((lane >> 4) & 1) * 8 + (lane & 7));
    const uint32_t b_cb  = (uint32_t)(((lane >> 3) & 1) * 16);

    for (int tile = blockIdx.x; tile < ntiles; tile += gridDim.x) {
        int t2 = tile;
        float* Cw = C;
        size_t kbase = 0;
        if (tile >= ntHalf) {
            t2 = tile - ntHalf;
            Cw = C2;
            kbase = (size_t)Kiter;
        }
        const int nBase = (t2 % tilesX) * 128;
        const int mBase = (t2 / tilesX) * MROWS;

        float acc[MF][4][4];
        #pragma unroll
        for (int a = 0; a < MF; ++a)
            #pragma unroll
            for (int b = 0; b < 4; ++b)
                #pragma unroll
                for (int c = 0; c < 4; ++c) acc[a][b][c] = 0.f;

        auto load_stage = [&](int stg, int s) {
            uint32_t base = sb + (uint32_t)stg * STAGE;
            #pragma unroll
            for (int q = 0; q < 2; ++q) {
                const size_t koff = kbase + (size_t)s * 32 + (size_t)q * 16;
                uint32_t sbase = base + (uint32_t)q * SLICE;
                #pragma unroll
                for (int i = 0; i < CPT; ++i) {
                    const __nv_bfloat16* src;
                    size_t goff;
                    if (larr[i] < 2) {
                        src  = (larr[i] == 0) ? Ahi : Alo;
                        goff = (size_t)(mBase + lrow[i]) * ld + koff + (size_t)lch[i] * 8;
                    } else {
                        src  = (larr[i] == 2) ? Bhi : Blo;
                        goff = (size_t)(nBase + lrow[i]) * ld + koff + (size_t)lch[i] * 8;
                    }
                    cpasync16(sbase + lsw[i], src + goff);
                }
            }
            asm volatile("cp.async.commit_group;" ::: "memory");
        };

        load_stage(0, 0);
        load_stage(1, 1);

        for (int s = 0; s < nst; ++s) {
            if (s < nst - 1) asm volatile("cp.async.wait_group 1;" ::: "memory");
            else             asm volatile("cp.async.wait_group 0;" ::: "memory");
            __syncthreads();

            const uint32_t stg = sb + (uint32_t)(s % NSTAGE) * STAGE;

            #pragma unroll
            for (int q = 0; q < 2; ++q) {
                const uint32_t sAhi = stg + (uint32_t)q * SLICE;
                const uint32_t sAlo = sAhi + ABYTES;
                const uint32_t sBhi = sAhi + 2 * ABYTES;
                const uint32_t sBlo = sBhi + 4096;

                uint32_t bh[4][2], bl[4][2];
                #pragma unroll
                for (int nf2 = 0; nf2 < 2; ++nf2) {
                    uint32_t off = sw32((b_row + (uint32_t)nf2 * 16u) * 32u + b_cb);
                    uint32_t r[4];
                    ldsm4(r, sBhi + off);
                    bh[nf2*2][0] = r[0]; bh[nf2*2][1] = r[1];
                    bh[nf2*2+1][0] = r[2]; bh[nf2*2+1][1] = r[3];
                    ldsm4(r, sBlo + off);
                    bl[nf2*2][0] = r[0]; bl[nf2*2][1] = r[1];
                    bl[nf2*2+1][0] = r[2]; bl[nf2*2+1][1] = r[3];
                }
                uint32_t ah[MF][4], al[MF][4];
                #pragma unroll
                for (int mf = 0; mf < MF; ++mf) {
                    uint32_t off = sw32((a_row + (uint32_t)mf * 16u) * 32u + a_cb);
                    ldsm4(ah[mf], sAhi + off);
                    ldsm4(al[mf], sAlo + off);
                }

                #pragma unroll
                for (int mf = 0; mf < MF; ++mf)
                    #pragma unroll
                    for (int nf = 0; nf < 4; ++nf)
                        mma16816(acc[mf][nf], ah[mf], bh[nf]);
                #pragma unroll
                for (int mf = 0; mf < MF; ++mf)
                    #pragma unroll
                    for (int nf = 0; nf < 4; ++nf)
                        mma16816(acc[mf][nf], ah[mf], bl[nf]);
                #pragma unroll
                for (int mf = 0; mf < MF; ++mf)
                    #pragma unroll
                    for (int nf = 0; nf < 4; ++nf)
                        mma16816(acc[mf][nf], al[mf], bh[nf]);
            }
            if (s + 2 < nst) load_stage((s + 2) % NSTAGE, s + 2);
        }

        const int gid = lane >> 2;
        const int tig = lane & 3;
        #pragma unroll
        for (int mf = 0; mf < MF; ++mf) {
            int row0 = mBase + wmB + mf * 16 + gid;
            #pragma unroll
            for (int nf = 0; nf < 4; ++nf) {
                int col = nBase + wnB + nf * 8 + tig * 2;
                if (col < Nreal) {
                    float2 v0 = make_float2(acc[mf][nf][0], acc[mf][nf][1]);
                    float2 v1 = make_float2(acc[mf][nf][2], acc[mf][nf][3]);
                    *(float2*)(Cw + (size_t)row0 * Nreal + col) = v0;
                    *(float2*)(Cw + (size_t)(row0 + 8) * Nreal + col) = v1;
                }
            }
        }
        __syncthreads();
    }
}

// ---------------- add partial: out += part -----------------------------------
__global__ void __launch_bounds__(256)
add_partial(float* __restrict__ out, const float* __restrict__ part, int count)
{
    int i = (blockIdx.x * 256 + threadIdx.x) * 4;
    if (i >= count) return;
    float4 a = *(const float4*)(out + i);
    float4 b = *(const float4*)(part + i);
    *(float4*)(out + i) = make_float4(a.x + b.x, a.y + b.y, a.z + b.z, a.w + b.w);
}

// ---------------- dt projection + softplus ------------------------------------
__global__ void __launch_bounds__(256)
dt_kernel(const float* __restrict__ W_dt, const float* __restrict__ dt_bias)
{
    __shared__ float s_r[64 * DT_RANK];
    const int t0 = blockIdx.x * 64;
    const int d  = blockIdx.y * 256 + threadIdx.x;

    #pragma unroll
    for (int k = 0; k < 16; ++k) {
        int idx = threadIdx.x + k * 256;
        int row = idx >> 6, col = idx & 63;
        s_r[idx] = g_zx[(size_t)(t0 + row) * D_PROJ + OFF_DT + col];
    }
    __syncthreads();

    float w[DT_RANK];
    #pragma unroll
    for (int k = 0; k < DT_RANK; ++k)
        w[k] = W_dt[(size_t)k * D_INNER + d];

    const float bias2 = 2.f * dt_bias[d];

    for (int tt = 0; tt < 64; ++tt) {
        const float4* rp = (const float4*)(s_r + tt * DT_RANK);
        float s = bias2;
        #pragma unroll
        for (int k4 = 0; k4 < DT_RANK / 4; ++k4) {
            float4 r4 = rp[k4];
            s = fmaf(r4.x, w[k4*4+0], s);
            s = fmaf(r4.y, w[k4*4+1], s);
            s = fmaf(r4.z, w[k4*4+2], s);
            s = fmaf(r4.w, w[k4*4+3], s);
        }
        float sp = (s > 20.f) ? s : log1pf(__expf(s));
        g_delta[(size_t)(t0 + tt) * D_INNER + d] = sp;
    }
}

// ---------------- causal depthwise conv (K=4) + bias + silu -------------------
__global__ void __launch_bounds__(256)
conv_kernel(const float* __restrict__ w, const float* __restrict__ b)
{
    int idx = blockIdx.x * blockDim.x + threadIdx.x;
    if (idx >= L_SEQ * D_XB) return;
    int t = idx >> 9, c = idx & (D_XB - 1);
    float acc = b[c];
    #pragma unroll
    for (int k = 0; k < KCONV; ++k) {
        int tt = t - (KCONV - 1) + k;
        if (tt >= 0)
            acc = fmaf(w[c * KCONV + k], g_zx[(size_t)tt * D_PROJ + OFF_X + c], acc);
    }
    g_xconv[idx] = acc / (1.f + __expf(-acc));
}

// ---------------- scan: thread owns all 16 states of one d-channel -----------
// grid (NCH, 8): chunk j, d-block db (256 d's). Phase A: local (P,E).
__global__ void __launch_bounds__(256)
scan_phase_a(const float* __restrict__ A_log)
{
    __shared__ float s_xv[CH * 64], s_B[CH * 64];
    const int j   = blockIdx.x;
    const int db  = blockIdx.y;
    const int tid = threadIdx.x;
    const int d   = db * 256 + tid;
    const int tbase = j * CH;

    #pragma unroll
    for (int k = 0; k < 8; ++k) {
        int i = tid + k * 256;
        int t = i >> 6, c = i & 63;
        s_xv[i] = g_xconv[(size_t)(tbase + t) * D_XB + db * 64 + c];
        s_B [i] = g_zx[(size_t)(tbase + t) * D_PROJ + OFF_B + db * 64 + c];
    }
    __syncthreads();

    float A[16], h[16], P[16];
    #pragma unroll
    for (int n = 0; n < 16; ++n) {
        A[n] = -expf(A_log[(size_t)d * 16 + n]);
        h[n] = 0.f; P[n] = 1.f;
    }
    const int xc  = ((tid >> 6) << 4) + (tid & 15);
    const int gxl = (tid >> 6) << 4;

    for (int t = 0; t < CH; ++t) {
        float dv = g_delta[(size_t)(tbase + t) * D_INNER + d];
        float dx = dv * s_xv[t * 64 + xc];
        const float4* bp = (const float4*)(s_B + t * 64 + gxl);
        float4 b4[4] = {bp[0], bp[1], bp[2], bp[3]};
        const float* bb = (const float*)b4;
        #pragma unroll
        for (int n = 0; n < 16; ++n) {
            float a = __expf(dv * A[n]);
            P[n] *= a;
            h[n] = fmaf(a, h[n], dx * bb[n]);
        }
    }
    float* Pp = g_cP + ((size_t)j * D_INNER + d) * 16;
    float* Ep = g_cE + ((size_t)j * D_INNER + d) * 16;
    #pragma unroll
    for (int n4 = 0; n4 < 4; ++n4) {
        *(float4*)(Pp + n4 * 4) = make_float4(P[n4*4], P[n4*4+1], P[n4*4+2], P[n4*4+3]);
        *(float4*)(Ep + n4 * 4) = make_float4(h[n4*4], h[n4*4+1], h[n4*4+2], h[n4*4+3]);
    }
}

// Phase B: sequential combine over NCH chunks; thread owns one (d,n) cell.
__global__ void __launch_bounds__(256)
scan_phase_b()
{
    int idx = blockIdx.x * 256 + threadIdx.x;      // 0 .. 32767
    float c = 0.f;
    #pragma unroll 4
    for (int j = 0; j < NCH; ++j) {
        size_t o = (size_t)j * (D_INNER * 16) + idx;
        g_cC[o] = c;
        c = fmaf(g_cP[o], c, g_cE[o]);
    }
}

// Phase C: replay with carry, in-register y accumulation, gate, write bf16 yg.
__global__ void __launch_bounds__(256)
scan_phase_c(const float* __restrict__ A_log, const float* __restrict__ Dp)
{
    __shared__ float s_xv[CH * 64], s_B[CH * 64], s_C[CH * 256];
    const int j   = blockIdx.x;
    const int db  = blockIdx.y;
    const int tid = threadIdx.x;
    const int d   = db * 256 + tid;
    const int tbase = j * CH;

    #pragma unroll
    for (int k = 0; k < 8; ++k) {
        int i = tid + k * 256;
        int t = i >> 6, c = i & 63;
        s_xv[i] = g_xconv[(size_t)(tbase + t) * D_XB + db * 64 + c];
        s_B [i] = g_zx[(size_t)(tbase + t) * D_PROJ + OFF_B + db * 64 + c];
    }
    #pragma unroll
    for (int k = 0; k < 32; ++k) {
        int i = tid + k * 256;
        int t = i >> 8, c = i & 255;
        s_C[i] = g_zx[(size_t)(tbase + t) * D_PROJ + OFF_C + db * 256 + c];
    }
    __syncthreads();

    float A[16], h[16];
    const float* Cp = g_cC + ((size_t)j * D_INNER + d) * 16;
    #pragma unroll
    for (int n = 0; n < 16; ++n) {
        A[n] = -expf(A_log[(size_t)d * 16 + n]);
        h[n] = Cp[n];
    }
    const float Dv = Dp[d];
    const int xc  = ((tid >> 6) << 4) + (tid & 15);
    const int gxl = (tid >> 6) << 4;
    const int gl  = tid & 0xF0;           // g-local * 16

    for (int t = 0; t < CH; ++t) {
        float dv = g_delta[(size_t)(tbase + t) * D_INNER + d];
        float xv = s_xv[t * 64 + xc];
        float dx = dv * xv;
        const float4* bp = (const float4*)(s_B + t * 64 + gxl);
        float4 b4[4] = {bp[0], bp[1], bp[2], bp[3]};
        const float* bb = (const float*)b4;
        const float4* cp = (const float4*)(s_C + t * 256 + gl);
        float4 c4[4] = {cp[0], cp[1], cp[2], cp[3]};
        const float* cc = (const float*)c4;

        float y = 0.f;
        #pragma unroll
        for (int n = 0; n < 16; ++n) {
            float a = __expf(dv * A[n]);
            h[n] = fmaf(a, h[n], dx * bb[n]);
            y = fmaf(h[n], cc[n], y);
        }
        float zv = g_zx[(size_t)(tbase + t) * D_PROJ + OFF_Z + d];
        float sz = zv / (1.f + __expf(-zv));
        float yv = (y + Dv * xv) * sz;
        size_t oi = (size_t)(tbase + t) * D_INNER + d;
        __nv_bfloat16 hb = __float2bfloat16_rn(yv);
        g_ahi[oi] = hb;
        g_alo[oi] = __float2bfloat16_rn(yv - __bfloat162float(hb));
    }
}

// ---------------- launch ------------------------------------------------------
extern "C" void kernel_launch(void* const* d_in, const int* in_sizes, int n_in,
                              void* d_out, int out_size)
{
    const float* hidden  = (const float*)d_in[0];
    const float* W_in    = (const float*)d_in[1];
    const float* conv_w  = (const float*)d_in[2];
    const float* conv_b  = (const float*)d_in[3];
    const float* W_dt    = (const float*)d_in[4];
    const float* dt_bias = (const float*)d_in[5];
    const float* A_log   = (const float*)d_in[6];
    const float* Dp      = (const float*)d_in[7];
    const float* W_out   = (const float*)d_in[8];
    float*       out     = (float*)d_out;

    cudaFuncSetAttribute(gemm_tc_kernel,
                         cudaFuncAttributeMaxDynamicSharedMemorySize, GEMM_SMEM);

    float *zx, *gpart;
    __nv_bfloat16 *ahi, *alo, *w1hi, *w1lo, *w2hi, *w2lo;
    cudaGetSymbolAddress((void**)&zx,    g_zx);
    cudaGetSymbolAddress((void**)&gpart, g_part);
    cudaGetSymbolAddress((void**)&ahi,   g_ahi);
    cudaGetSymbolAddress((void**)&alo,   g_alo);
    cudaGetSymbolAddress((void**)&w1hi,  g_w1hi);
    cudaGetSymbolAddress((void**)&w1lo,  g_w1lo);
    cudaGetSymbolAddress((void**)&w2hi,  g_w2hi);
    cudaGetSymbolAddress((void**)&w2lo,  g_w2lo);

    // 1-3) operand prep (GEMM1 in profiled slot 4)
    transpose_wt<<<dim3(NPAD1 / 32, D_MODEL / 32), 256>>>(W_in, w1hi, w1lo, D_MODEL, D_PROJ);
    transpose_wt<<<dim3(D_MODEL / 32, D_INNER / 32), 256>>>(W_out, w2hi, w2lo, D_INNER, D_MODEL);
    convert_hilo<<<(L_SEQ * D_MODEL) / 1024, 256>>>(hidden, ahi, alo, L_SEQ * D_MODEL);

    // 4) zxbcdt = hidden @ W_in — 128x128 tiles, 592 persistent workers
    {
        int tilesX = NPAD1 / 128;                   // 41
        int ntiles = tilesX * (L_SEQ / 128);        // 656
        gemm_tc_kernel<<<592, 256, GEMM_SMEM>>>(
            ahi, alo, w1hi, w1lo, zx, zx,
            D_PROJ, D_MODEL, D_MODEL, tilesX, ntiles, ntiles);
    }

    // 5-6) delta + conv
    dt_kernel<<<dim3(L_SEQ / 64, D_INNER / 256), 256>>>(W_dt, dt_bias);
    conv_kernel<<<(L_SEQ * D_XB + 255) / 256, 256>>>(conv_w, conv_b);

    // 7-9) chunked scan, register-state layout (phase C writes bf16 yg)
    scan_phase_a<<<dim3(NCH, 8), 256>>>(A_log);
    scan_phase_b<<<(D_INNER * 16) / 256, 256>>>();
    scan_phase_c<<<dim3(NCH, 8), 256>>>(A_log, Dp);

    // 10) out = yg @ W_out — K-split, 256 CTAs coresident
    {
        int tilesX = D_MODEL / 128;                 // 8
        int ntHalf = tilesX * (L_SEQ / 128);        // 128
        gemm_tc_kernel<<<256, 256, GEMM_SMEM>>>(
            ahi, alo, w2hi, w2lo, out, gpart,
            D_MODEL, D_INNER / 2, D_INNER, tilesX, 2 * ntHalf, ntHalf);
    }
    // 11) out += partial
    add_partial<<<(L_SEQ * D_MODEL) / 1024, 256>>>(out, gpart, L_SEQ * D_MODEL);
}

// round 15
// speedup vs baseline: 1.3653x; 1.0517x over previous
#include <cuda_runtime.h>
#include <cuda_bf16.h>
#include <cstdint>

// ---------------- problem constants ----------------
#define L_SEQ    2048
#define D_MODEL  1024
#define D_INNER  2048
#define D_XB     512
#define D_STATE  16
#define DT_RANK  64
#define KCONV    4
#define G_HEADS  128
#define GX_HEADS 32
#define D_PROJ   5184
#define NPAD1    5248          // D_PROJ padded to multiple of 128

#define OFF_Z    0
#define OFF_X    2048
#define OFF_B    2560
#define OFF_C    3072
#define OFF_DT   5120

// scan chunking: 32 timesteps per chunk, 64 chunks
#define CH       32
#define NCH      64

// ---------------- scratch (static device globals; no runtime allocation) ----
__device__ float g_zx   [L_SEQ * D_PROJ];
__device__ float g_delta[L_SEQ * D_INNER];
__device__ float g_xconv[L_SEQ * D_XB];
__device__ float g_part [L_SEQ * D_MODEL];     // GEMM2 k-split partial

// scan carries
__device__ float g_cS [NCH * D_INNER];                 // sum of dv per (chunk,d)
__device__ float g_cE [NCH * D_INNER * D_STATE];       // local end state
__device__ float g_cC [NCH * D_INNER * D_STATE];       // carry-in

__device__ __nv_bfloat16 g_ahi [L_SEQ * D_INNER];
__device__ __nv_bfloat16 g_alo [L_SEQ * D_INNER];
__device__ __nv_bfloat16 g_w1hi[NPAD1 * D_MODEL];
__device__ __nv_bfloat16 g_w1lo[NPAD1 * D_MODEL];
__device__ __nv_bfloat16 g_w2hi[D_MODEL * D_INNER];
__device__ __nv_bfloat16 g_w2lo[D_MODEL * D_INNER];

// ================= low-level helpers =========================================
__device__ __forceinline__ uint32_t smem_u32(const void* p) {
    return (uint32_t)__cvta_generic_to_shared(p);
}
__device__ __forceinline__ void cpasync16(uint32_t saddr, const void* g) {
    asm volatile("cp.async.cg.shared.global [%0], [%1], 16;" :: "r"(saddr), "l"(g));
}
__device__ __forceinline__ void ldsm4(uint32_t* r, uint32_t addr) {
    asm volatile("ldmatrix.sync.aligned.m8n8.x4.shared.b16 {%0,%1,%2,%3}, [%4];"
        : "=r"(r[0]), "=r"(r[1]), "=r"(r[2]), "=r"(r[3]) : "r"(addr));
}
__device__ __forceinline__ void mma16816(float* d, const uint32_t* a, const uint32_t* b) {
    asm volatile("mma.sync.aligned.m16n8k16.row.col.f32.bf16.bf16.f32 "
        "{%0,%1,%2,%3}, {%4,%5,%6,%7}, {%8,%9}, {%0,%1,%2,%3};"
        : "+f"(d[0]), "+f"(d[1]), "+f"(d[2]), "+f"(d[3])
        : "r"(a[0]), "r"(a[1]), "r"(a[2]), "r"(a[3]), "r"(b[0]), "r"(b[1]));
}
__device__ __forceinline__ uint32_t sw32(uint32_t off) {
    return off ^ ((off >> 3) & 0x70);
}

// ================= fp32 -> bf16 hi/lo conversion =============================
__global__ void __launch_bounds__(256)
convert_hilo(const float* __restrict__ in, __nv_bfloat16* __restrict__ hi,
             __nv_bfloat16* __restrict__ lo, int count)
{
    int i = (blockIdx.x * 256 + threadIdx.x) * 4;
    if (i >= count) return;
    float4 v = *(const float4*)(in + i);
    float vv[4] = {v.x, v.y, v.z, v.w};
    __nv_bfloat16 h[4], l[4];
    #pragma unroll
    for (int j = 0; j < 4; ++j) {
        h[j] = __float2bfloat16_rn(vv[j]);
        l[j] = __float2bfloat16_rn(vv[j] - __bfloat162float(h[j]));
    }
    *(uint2*)(hi + i) = *(uint2*)h;
    *(uint2*)(lo + i) = *(uint2*)l;
}

// ================= transpose W [K,N] -> [Npad,K] bf16 hi/lo ==================
__global__ void __launch_bounds__(256)
transpose_wt(const float* __restrict__ W, __nv_bfloat16* __restrict__ Thi,
             __nv_bfloat16* __restrict__ Tlo, int K, int N)
{
    __shared__ float tile[32][33];
    int n0 = blockIdx.x * 32;
    int k0 = blockIdx.y * 32;
    int tx = threadIdx.x & 31, ty = threadIdx.x >> 5;
    #pragma unroll
    for (int r = 0; r < 4; ++r) {
        int k = k0 + ty + r * 8;
        int n = n0 + tx;
        tile[ty + r * 8][tx] = (n < N) ? W[(size_t)k * N + n] : 0.f;
    }
    __syncthreads();
    #pragma unroll
    for (int r = 0; r < 4; ++r) {
        int n = n0 + ty + r * 8;
        int k = k0 + tx;
        float v = tile[tx][ty + r * 8];
        __nv_bfloat16 h = __float2bfloat16_rn(v);
        Thi[(size_t)n * K + k] = h;
        Tlo[(size_t)n * K + k] = __float2bfloat16_rn(v - __bfloat162float(h));
    }
}

// ================= split-bf16 warp-MMA GEMM (persistent + optional K-split) ==
#define NSTAGE   3
#define MF       4
#define MROWS    (MF * 32)
#define ABYTES   (MROWS * 32)
#define SLICE    (2 * ABYTES + 8192)
#define STAGE    (2 * SLICE)
#define GEMM_SMEM (NSTAGE * STAGE)     // 96KB

__global__ void __launch_bounds__(256, 2)
gemm_tc_kernel(const __nv_bfloat16* __restrict__ Ahi, const __nv_bfloat16* __restrict__ Alo,
               const __nv_bfloat16* __restrict__ Bhi, const __nv_bfloat16* __restrict__ Blo,
               float* __restrict__ C, float* __restrict__ C2,
               int Nreal, int Kiter, int ld, int tilesX, int ntiles, int ntHalf)
{
    constexpr int ACH = MROWS * 2;
    constexpr int CPT = (MROWS * 4 + 512) / 256;

    extern __shared__ char sm[];
    const uint32_t sb = smem_u32(sm);
    const int tid   = threadIdx.x;
    const int lane  = tid & 31;
    const int wid   = tid >> 5;
    const int wmB   = (wid >> 2) * (MF * 16);
    const int wnB   = (wid & 3) * 32;

    const int nst = Kiter >> 5;

    int lrow[CPT], lch[CPT], larr[CPT];
    uint32_t lsw[CPT];
    #pragma unroll
    for (int i = 0; i < CPT; ++i) {
        int idx = tid + i * 256;
        if (idx < 2 * ACH) {
            larr[i] = idx / ACH;
            int w = idx % ACH;
            lrow[i] = w >> 1; lch[i] = w & 1;
            lsw[i]  = (uint32_t)larr[i] * ABYTES
                    + sw32((uint32_t)lrow[i] * 32u + (uint32_t)lch[i] * 16u);
        } else {
            int rem = idx - 2 * ACH;
            int bl  = rem >> 8;
            larr[i] = 2 + bl;
            int w = rem & 255;
            lrow[i] = w >> 1; lch[i] = w & 1;
            lsw[i]  = 2u * ABYTES + (uint32_t)bl * 4096u
                    + sw32((uint32_t)lrow[i] * 32u + (uint32_t)lch[i] * 16u);
        }
    }

    const uint32_t a_row = (uint32_t)(wmB + (lane & 15));
    const uint32_t a_cb  = (uint32_t)((lane >> 4) * 16);
    const uint32_t b_row = (uint32_t)(wnB + ((lane >> 4) & 1) * 8 + (lane & 7));
    const uint32_t b_cb  = (uint32_t)(((lane >> 3) & 1) * 16);

    for (int tile = blockIdx.x; tile < ntiles; tile += gridDim.x) {
        int t2 = tile;
        float* Cw = C;
        size_t kbase = 0;
        if (tile >= ntHalf) {
            t2 = tile - ntHalf;
            Cw = C2;
            kbase = (size_t)Kiter;
        }
        const int nBase = (t2 % tilesX) * 128;
        const int mBase = (t2 / tilesX) * MROWS;

        float acc[MF][4][4];
        #pragma unroll
        for (int a = 0; a < MF; ++a)
            #pragma unroll
            for (int b = 0; b < 4; ++b)
                #pragma unroll
                for (int c = 0; c < 4; ++c) acc[a][b][c] = 0.f;

        auto load_stage = [&](int stg, int s) {
            uint32_t base = sb + (uint32_t)stg * STAGE;
            #pragma unroll
            for (int q = 0; q < 2; ++q) {
                const size_t koff = kbase + (size_t)s * 32 + (size_t)q * 16;
                uint32_t sbase = base + (uint32_t)q * SLICE;
                #pragma unroll
                for (int i = 0; i < CPT; ++i) {
                    const __nv_bfloat16* src;
                    size_t goff;
                    if (larr[i] < 2) {
                        src  = (larr[i] == 0) ? Ahi : Alo;
                        goff = (size_t)(mBase + lrow[i]) * ld + koff + (size_t)lch[i] * 8;
                    } else {
                        src  = (larr[i] == 2) ? Bhi : Blo;
                        goff = (size_t)(nBase + lrow[i]) * ld + koff + (size_t)lch[i] * 8;
                    }
                    cpasync16(sbase + lsw[i], src + goff);
                }
            }
            asm volatile("cp.async.commit_group;" ::: "memory");
        };

        load_stage(0, 0);
        load_stage(1, 1);

        for (int s = 0; s < nst; ++s) {
            if (s < nst - 1) asm volatile("cp.async.wait_group 1;" ::: "memory");
            else             asm volatile("cp.async.wait_group 0;" ::: "memory");
            __syncthreads();

            const uint32_t stg = sb + (uint32_t)(s % NSTAGE) * STAGE;

            #pragma unroll
            for (int q = 0; q < 2; ++q) {
                const uint32_t sAhi = stg + (uint32_t)q * SLICE;
                const uint32_t sAlo = sAhi + ABYTES;
                const uint32_t sBhi = sAhi + 2 * ABYTES;
                const uint32_t sBlo = sBhi + 4096;

                uint32_t bh[4][2], bl[4][2];
                #pragma unroll
                for (int nf2 = 0; nf2 < 2; ++nf2) {
                    uint32_t off = sw32((b_row + (uint32_t)nf2 * 16u) * 32u + b_cb);
                    uint32_t r[4];
                    ldsm4(r, sBhi + off);
                    bh[nf2*2][0] = r[0]; bh[nf2*2][1] = r[1];
                    bh[nf2*2+1][0] = r[2]; bh[nf2*2+1][1] = r[3];
                    ldsm4(r, sBlo + off);
                    bl[nf2*2][0] = r[0]; bl[nf2*2][1] = r[1];
                    bl[nf2*2+1][0] = r[2]; bl[nf2*2+1][1] = r[3];
                }
                uint32_t ah[MF][4], al[MF][4];
                #pragma unroll
                for (int mf = 0; mf < MF; ++mf) {
                    uint32_t off = sw32((a_row + (uint32_t)mf * 16u) * 32u + a_cb);
                    ldsm4(ah[mf], sAhi + off);
                    ldsm4(al[mf], sAlo + off);
                }

                #pragma unroll
                for (int mf = 0; mf < MF; ++mf)
                    #pragma unroll
                    for (int nf = 0; nf < 4; ++nf)
                        mma16816(acc[mf][nf], ah[mf], bh[nf]);
                #pragma unroll
                for (int mf = 0; mf < MF; ++mf)
                    #pragma unroll
                    for (int nf = 0; nf < 4; ++nf)
                        mma16816(acc[mf][nf], ah[mf], bl[nf]);
                #pragma unroll
                for (int mf = 0; mf < MF; ++mf)
                    #pragma unroll
                    for (int nf = 0; nf < 4; ++nf)
                        mma16816(acc[mf][nf], al[mf], bh[nf]);
            }
            if (s + 2 < nst) load_stage((s + 2) % NSTAGE, s + 2);
        }

        const int gid = lane >> 2;
        const int tig = lane & 3;
        #pragma unroll
        for (int mf = 0; mf < MF; ++mf) {
            int row0 = mBase + wmB + mf * 16 + gid;
            #pragma unroll
            for (int nf = 0; nf < 4; ++nf) {
                int col = nBase + wnB + nf * 8 + tig * 2;
                if (col < Nreal) {
                    float2 v0 = make_float2(acc[mf][nf][0], acc[mf][nf][1]);
                    float2 v1 = make_float2(acc[mf][nf][2], acc[mf][nf][3]);
                    *(float2*)(Cw + (size_t)row0 * Nreal + col) = v0;
                    *(float2*)(Cw + (size_t)(row0 + 8) * Nreal + col) = v1;
                }
            }
        }
        __syncthreads();
    }
}

// ---------------- add partial: out += part -----------------------------------
__global__ void __launch_bounds__(256)
add_partial(float* __restrict__ out, const float* __restrict__ part, int count)
{
    int i = (blockIdx.x * 256 + threadIdx.x) * 4;
    if (i >= count) return;
    float4 a = *(const float4*)(out + i);
    float4 b = *(const float4*)(part + i);
    *(float4*)(out + i) = make_float4(a.x + b.x, a.y + b.y, a.z + b.z, a.w + b.w);
}

// ---------------- dt projection + softplus (persistent fine tiles) -----------
// tile = 16 t-rows x 256 d-cols; 1024 tiles; grid 296 persistent workers.
#define DT_TILES 1024
__global__ void __launch_bounds__(256, 2)
dt_kernel(const float* __restrict__ W_dt, const float* __restrict__ dt_bias)
{
    __shared__ float s_r[16 * DT_RANK];   // 4KB
    const int tid = threadIdx.x;

    for (int tile = blockIdx.x; tile < DT_TILES; tile += gridDim.x) {
        const int t0 = (tile >> 3) * 16;
        const int db = tile & 7;
        const int d  = db * 256 + tid;

        __syncthreads();   // protect s_r reuse across tiles
        #pragma unroll
        for (int k = 0; k < 4; ++k) {
            int idx = tid + k * 256;
            int row = idx >> 6, col = idx & 63;
            s_r[idx] = g_zx[(size_t)(t0 + row) * D_PROJ + OFF_DT + col];
        }
        __syncthreads();

        float w[DT_RANK];
        #pragma unroll
        for (int k = 0; k < DT_RANK; ++k)
            w[k] = W_dt[(size_t)k * D_INNER + d];

        const float bias2 = 2.f * dt_bias[d];

        #pragma unroll 4
        for (int tt = 0; tt < 16; ++tt) {
            const float4* rp = (const float4*)(s_r + tt * DT_RANK);
            float s = bias2;
            #pragma unroll
            for (int k4 = 0; k4 < DT_RANK / 4; ++k4) {
                float4 r4 = rp[k4];
                s = fmaf(r4.x, w[k4*4+0], s);
                s = fmaf(r4.y, w[k4*4+1], s);
                s = fmaf(r4.z, w[k4*4+2], s);
                s = fmaf(r4.w, w[k4*4+3], s);
            }
            float sp = (s > 20.f) ? s : log1pf(__expf(s));
            g_delta[(size_t)(t0 + tt) * D_INNER + d] = sp;
        }
    }
}

// ---------------- causal depthwise conv (K=4) + bias + silu -------------------
__global__ void __launch_bounds__(256)
conv_kernel(const float* __restrict__ w, const float* __restrict__ b)
{
    int idx = blockIdx.x * blockDim.x + threadIdx.x;
    if (idx >= L_SEQ * D_XB) return;
    int t = idx >> 9, c = idx & (D_XB - 1);
    float acc = b[c];
    #pragma unroll
    for (int k = 0; k < KCONV; ++k) {
        int tt = t - (KCONV - 1) + k;
        if (tt >= 0)
            acc = fmaf(w[c * KCONV + k], g_zx[(size_t)tt * D_PROJ + OFF_X + c], acc);
    }
    g_xconv[idx] = acc / (1.f + __expf(-acc));
}

// ---------------- scan phase A: local scan; stores E and S = sum(dv) ---------
__global__ void __launch_bounds__(256)
scan_phase_a(const float* __restrict__ A_log)
{
    __shared__ float s_xv[CH * 64], s_B[CH * 64];
    const int j   = blockIdx.x;
    const int db  = blockIdx.y;
    const int tid = threadIdx.x;
    const int d   = db * 256 + tid;
    const int tbase = j * CH;

    #pragma unroll
    for (int k = 0; k < 8; ++k) {
        int i = tid + k * 256;
        int t = i >> 6, c = i & 63;
        s_xv[i] = g_xconv[(size_t)(tbase + t) * D_XB + db * 64 + c];
        s_B [i] = g_zx[(size_t)(tbase + t) * D_PROJ + OFF_B + db * 64 + c];
    }
    __syncthreads();

    float A[16], h[16];
    #pragma unroll
    for (int n = 0; n < 16; ++n) {
        A[n] = -expf(A_log[(size_t)d * 16 + n]);
        h[n] = 0.f;
    }
    float S = 0.f;
    const int xc  = ((tid >> 6) << 4) + (tid & 15);
    const int gxl = (tid >> 6) << 4;

    float dv_next = g_delta[(size_t)tbase * D_INNER + d];
    #pragma unroll 4
    for (int t = 0; t < CH; ++t) {
        float dv = dv_next;
        if (t + 1 < CH) dv_next = g_delta[(size_t)(tbase + t + 1) * D_INNER + d];
        S += dv;
        float dx = dv * s_xv[t * 64 + xc];
        const float4* bp = (const float4*)(s_B + t * 64 + gxl);
        float4 b4[4] = {bp[0], bp[1], bp[2], bp[3]};
        const float* bb = (const float*)b4;
        #pragma unroll
        for (int n = 0; n < 16; ++n) {
            float a = __expf(dv * A[n]);
            h[n] = fmaf(a, h[n], dx * bb[n]);
        }
    }
    float* Ep = g_cE + ((size_t)j * D_INNER + d) * 16;
    #pragma unroll
    for (int n4 = 0; n4 < 4; ++n4)
        *(float4*)(Ep + n4 * 4) = make_float4(h[n4*4], h[n4*4+1], h[n4*4+2], h[n4*4+3]);
    g_cS[(size_t)j * D_INNER + d] = S;
}

// Phase B: carry chain; P reconstructed as exp(A * S). Thread owns one (d,n).
__global__ void __launch_bounds__(256)
scan_phase_b(const float* __restrict__ A_log)
{
    int idx = blockIdx.x * 256 + threadIdx.x;      // 0 .. 32767 = d*16+n
    int d = idx >> 4;
    float A = -expf(A_log[idx]);
    float c = 0.f;
    #pragma unroll 4
    for (int j = 0; j < NCH; ++j) {
        float S = g_cS[(size_t)j * D_INNER + d];
        float P = __expf(A * S);
        size_t o = (size_t)j * (D_INNER * 16) + idx;
        g_cC[o] = c;
        c = fmaf(P, c, g_cE[o]);
    }
}

// Phase C: replay with carry, in-register y accumulation, gate, write bf16 yg.
__global__ void __launch_bounds__(256)
scan_phase_c(const float* __restrict__ A_log, const float* __restrict__ Dp)
{
    __shared__ float s_xv[CH * 64], s_B[CH * 64], s_C[CH * 256];
    const int j   = blockIdx.x;
    const int db  = blockIdx.y;
    const int tid = threadIdx.x;
    const int d   = db * 256 + tid;
    const int tbase = j * CH;

    #pragma unroll
    for (int k = 0; k < 8; ++k) {
        int i = tid + k * 256;
        int t = i >> 6, c = i & 63;
        s_xv[i] = g_xconv[(size_t)(tbase + t) * D_XB + db * 64 + c];
        s_B [i] = g_zx[(size_t)(tbase + t) * D_PROJ + OFF_B + db * 64 + c];
    }
    #pragma unroll
    for (int k = 0; k < 32; ++k) {
        int i = tid + k * 256;
        int t = i >> 8, c = i & 255;
        s_C[i] = g_zx[(size_t)(tbase + t) * D_PROJ + OFF_C + db * 256 + c];
    }
    __syncthreads();

    float A[16], h[16];
    const float* Cp = g_cC + ((size_t)j * D_INNER + d) * 16;
    #pragma unroll
    for (int n = 0; n < 16; ++n) {
        A[n] = -expf(A_log[(size_t)d * 16 + n]);
        h[n] = Cp[n];
    }
    const float Dv = Dp[d];
    const int xc  = ((tid >> 6) << 4) + (tid & 15);
    const int gxl = (tid >> 6) << 4;
    const int gl  = tid & 0xF0;

    float dv_next = g_delta[(size_t)tbase * D_INNER + d];
    float zv_next = g_zx[(size_t)tbase * D_PROJ + OFF_Z + d];
    #pragma unroll 2
    for (int t = 0; t < CH; ++t) {
        float dv = dv_next;
        float zv = zv_next;
        if (t + 1 < CH) {
            dv_next = g_delta[(size_t)(tbase + t + 1) * D_INNER + d];
            zv_next = g_zx[(size_t)(tbase + t + 1) * D_PROJ + OFF_Z + d];
        }
        float xv = s_xv[t * 64 + xc];
        float dx = dv * xv;
        const float4* bp = (const float4*)(s_B + t * 64 + gxl);
        float4 b4[4] = {bp[0], bp[1], bp[2], bp[3]};
        const float* bb = (const float*)b4;
        const float4* cp = (const float4*)(s_C + t * 256 + gl);
        float4 c4[4] = {cp[0], cp[1], cp[2], cp[3]};
        const float* cc = (const float*)c4;

        float y = 0.f;
        #pragma unroll
        for (int n = 0; n < 16; ++n) {
            float a = __expf(dv * A[n]);
            h[n] = fmaf(a, h[n], dx * bb[n]);
            y = fmaf(h[n], cc[n], y);
        }
        float sz = zv / (1.f + __expf(-zv));
        float yv = (y + Dv * xv) * sz;
        size_t oi = (size_t)(tbase + t) * D_INNER + d;
        __nv_bfloat16 hb = __float2bfloat16_rn(yv);
        g_ahi[oi] = hb;
        g_alo[oi] = __float2bfloat16_rn(yv - __bfloat162float(hb));
    }
}

// ---------------- launch ------------------------------------------------------
extern "C" void kernel_launch(void* const* d_in, const int* in_sizes, int n_in,
                              void* d_out, int out_size)
{
    const float* hidden  = (const float*)d_in[0];
    const float* W_in    = (const float*)d_in[1];
    const float* conv_w  = (const float*)d_in[2];
    const float* conv_b  = (const float*)d_in[3];
    const float* W_dt    = (const float*)d_in[4];
    const float* dt_bias = (const float*)d_in[5];
    const float* A_log   = (const float*)d_in[6];
    const float* Dp      = (const float*)d_in[7];
    const float* W_out   = (const float*)d_in[8];
    float*       out     = (float*)d_out;

    cudaFuncSetAttribute(gemm_tc_kernel,
                         cudaFuncAttributeMaxDynamicSharedMemorySize, GEMM_SMEM);

    float *zx, *gpart;
    __nv_bfloat16 *ahi, *alo, *w1hi, *w1lo, *w2hi, *w2lo;
    cudaGetSymbolAddress((void**)&zx,    g_zx);
    cudaGetSymbolAddress((void**)&gpart, g_part);
    cudaGetSymbolAddress((void**)&ahi,   g_ahi);
    cudaGetSymbolAddress((void**)&alo,   g_alo);
    cudaGetSymbolAddress((void**)&w1hi,  g_w1hi);
    cudaGetSymbolAddress((void**)&w1lo,  g_w1lo);
    cudaGetSymbolAddress((void**)&w2hi,  g_w2hi);
    cudaGetSymbolAddress((void**)&w2lo,  g_w2lo);

    // 1-3) operand prep (GEMM1 in profiled slot 4)
    transpose_wt<<<dim3(NPAD1 / 32, D_MODEL / 32), 256>>>(W_in, w1hi, w1lo, D_MODEL, D_PROJ);
    transpose_wt<<<dim3(D_MODEL / 32, D_INNER / 32), 256>>>(W_out, w2hi, w2lo, D_INNER, D_MODEL);
    convert_hilo<<<(L_SEQ * D_MODEL) / 1024, 256>>>(hidden, ahi, alo, L_SEQ * D_MODEL);

    // 4) zxbcdt = hidden @ W_in — 128x128 tiles, 592 persistent workers
    {
        int tilesX = NPAD1 / 128;                   // 41
        int ntiles = tilesX * (L_SEQ / 128);        // 656
        gemm_tc_kernel<<<592, 256, GEMM_SMEM>>>(
            ahi, alo, w1hi, w1lo, zx, zx,
            D_PROJ, D_MODEL, D_MODEL, tilesX, ntiles, ntiles);
    }

    // 5-6) delta (persistent fine tiles) + conv
    dt_kernel<<<296, 256>>>(W_dt, dt_bias);
    conv_kernel<<<(L_SEQ * D_XB + 255) / 256, 256>>>(conv_w, conv_b);

    // 7-9) chunked scan, register-state layout with prefetch
    scan_phase_a<<<dim3(NCH, 8), 256>>>(A_log);
    scan_phase_b<<<(D_INNER * 16) / 256, 256>>>(A_log);
    scan_phase_c<<<dim3(NCH, 8), 256>>>(A_log, Dp);

    // 10) out = yg @ W_out — K-split, 256 CTAs coresident
    {
        int tilesX = D_MODEL / 128;                 // 8
        int ntHalf = tilesX * (L_SEQ / 128);        // 128
        gemm_tc_kernel<<<256, 256, GEMM_SMEM>>>(
            ahi, alo, w2hi, w2lo, out, gpart,
            D_MODEL, D_INNER / 2, D_INNER, tilesX, 2 * ntHalf, ntHalf);
    }
    // 11) out += partial
    add_partial<<<(L_SEQ * D_MODEL) / 1024, 256>>>(out, gpart, L_SEQ * D_MODEL);
}